// round 3
// baseline (speedup 1.0000x reference)
#include <cuda_runtime.h>
#include <math.h>

typedef unsigned long long ull;

#define THREADS 512
#define SPB 32          // samples per block (16 warps x 1 pair)
#define KT 96           // FC1 K-tile

// ---- shared float region (conv weights; later FC tiles; later head weights) ----
#define W1_OFF  0        // 16*27
#define B1_OFF  432      // 16
#define W2_OFF  448      // 32*145 (padded stride, conflict-free per-lane)
#define B2C_OFF 5088     // 32
#define W3_OFF  5120     // 64*289 (padded stride)
#define B3_OFF  23616    // 64
#define CW_FLOATS 23680
#define CW_BYTES  (CW_FLOATS * 4)          // 94720 B

#define A2_ULL (16 * 585)                  // feats per pair (584 used)
#define B2_ULL (16 * 289)                  // input/pooled scratch per pair
#define SMEM_BYTES (CW_BYTES + (A2_ULL + B2_ULL) * 8)   // 206592 B

// head weights in cw region (after FC1)
#define W2S  0           // ptw2 128*64
#define W3S  8192        // ptw3 64*2
#define B2SH 8320        // ptb2 64
#define B3SH 8384        // ptb3 2
#define CW2S 8386        // cfw2 64
#define CB2S 8450        // cfb2 1

// B2u (ull) region reuse after conv
#define T1_BASE 0        // 16*128
#define T2_BASE 2048     // 16*65
#define C1_BASE 3088     // 16*65

// ---- f32x2 helpers ----
__device__ __forceinline__ ull dup2(float w) {
    ull r; unsigned u = __float_as_uint(w);
    asm("mov.b64 %0, {%1, %1};" : "=l"(r) : "r"(u));
    return r;
}
__device__ __forceinline__ ull pk(float lo, float hi) {
    ull r;
    asm("mov.b64 %0, {%1, %2};" : "=l"(r)
        : "r"(__float_as_uint(lo)), "r"(__float_as_uint(hi)));
    return r;
}
__device__ __forceinline__ void unpk(ull v, float& lo, float& hi) {
    unsigned a, b;
    asm("mov.b64 {%0, %1}, %2;" : "=r"(a), "=r"(b) : "l"(v));
    lo = __uint_as_float(a); hi = __uint_as_float(b);
}
__device__ __forceinline__ void ffma2(ull& d, ull a, ull b) {
    asm("fma.rn.f32x2 %0, %1, %2, %0;" : "+l"(d) : "l"(a), "l"(b));
}
__device__ __forceinline__ ull fadd2(ull a, ull b) {
    ull r;
    asm("add.rn.f32x2 %0, %1, %2;" : "=l"(r) : "l"(a), "l"(b));
    return r;
}
__device__ __forceinline__ ull relu2(ull v) {
    float lo, hi; unpk(v, lo, hi);
    return pk(fmaxf(lo, 0.f), fmaxf(hi, 0.f));
}

__global__ void __launch_bounds__(THREADS, 1)
cqcnn_kernel(const float* __restrict__ gin,
             const float* __restrict__ c1w, const float* __restrict__ c1b,
             const float* __restrict__ c2w, const float* __restrict__ c2b,
             const float* __restrict__ c3w, const float* __restrict__ c3b,
             const float* __restrict__ qp,
             const float* __restrict__ ptw1, const float* __restrict__ ptb1,
             const float* __restrict__ ptw2, const float* __restrict__ ptb2,
             const float* __restrict__ ptw3, const float* __restrict__ ptb3,
             const float* __restrict__ cfw1, const float* __restrict__ cfb1,
             const float* __restrict__ cfw2, const float* __restrict__ cfb2,
             float* __restrict__ gout, int nsamp)
{
    extern __shared__ unsigned char smem[];
    float* cw  = (float*)smem;
    ull*  A2u  = (ull*)(smem + CW_BYTES);
    ull*  B2u  = A2u + A2_ULL;

    const int tid  = threadIdx.x;
    const int wid  = tid >> 5;
    const int lane = tid & 31;

    // ---------- conv weights -> shared ----------
    for (int i = tid; i < 16*27;  i += THREADS) cw[W1_OFF + i] = c1w[i];
    for (int i = tid; i < 32*144; i += THREADS)
        cw[W2_OFF + (i/144)*145 + (i%144)] = c2w[i];
    for (int i = tid; i < 64*288; i += THREADS)
        cw[W3_OFF + (i/288)*289 + (i%288)] = c3w[i];
    if (tid < 16) cw[B1_OFF + tid] = c1b[tid];
    else if (tid >= 64  && tid < 96)  cw[B2C_OFF + tid - 64]  = c2b[tid - 64];
    else if (tid >= 128 && tid < 192) cw[B3_OFF  + tid - 128] = c3b[tid - 128];

    // ---------- per-warp sample pair, interleaved f32x2 ----------
    const int s0  = blockIdx.x * SPB + wid * 2;
    const int s0c = min(s0,     nsamp - 1);
    const int s1c = min(s0 + 1, nsamp - 1);
    ull* Bw = B2u + wid * 289;     // input, later pooled conv2 out
    ull* Aw = A2u + wid * 585;     // conv1 out, later feats
    for (int i = lane; i < 108; i += 32)
        Bw[i] = pk(gin[(size_t)s0c * 108 + i], gin[(size_t)s1c * 108 + i]);
    __syncthreads();

    // ---------- quantum feature (lanes 0..7) ----------
    if (lane < 8) {
        float xl, xh, nl, nh;
        unpk(Bw[lane], xl, xh);
        unpk(Bw[(lane + 1) & 7], nl, nh);
        float ql = 0.f, qh = 0.f;
        #pragma unroll
        for (int l = 0; l < 3; l++) {
            float r0 = qp[(l*8 + lane)*3 + 0];
            float r1 = qp[(l*8 + lane)*3 + 1];
            float r2 = qp[(l*8 + lane)*3 + 2];
            ql = sinf(r0*xl) * cosf(r1*nl) + tanhf(r2*ql);
            qh = sinf(r0*xh) * cosf(r1*nh) + tanhf(r2*qh);
        }
        Aw[576 + lane] = pk(ql, qh);
    }

    // ---------- conv1: 3->16 on 6x6, pad1, relu ----------
    for (int it = 0; it < 18; it++) {
        int item = it*32 + lane;          // co*36 + pos
        int co  = item / 36;
        int pos = item - co*36;
        int y = pos / 6, x = pos - (pos/6)*6;
        ull acc = dup2(cw[B1_OFF + co]);
        const float* wr1 = cw + W1_OFF + co*27;
        #pragma unroll
        for (int dy = 0; dy < 3; dy++) {
            int yy = y + dy - 1;
            bool yok = (yy >= 0) && (yy < 6);
            #pragma unroll
            for (int dx = 0; dx < 3; dx++) {
                int xx = x + dx - 1;
                if (yok && xx >= 0 && xx < 6) {
                    #pragma unroll
                    for (int ci = 0; ci < 3; ci++)
                        ffma2(acc, dup2(wr1[ci*9 + dy*3 + dx]),
                              Bw[ci*36 + yy*6 + xx]);
                }
            }
        }
        Aw[item] = relu2(acc);
    }
    __syncwarp();

    // ---------- conv2: 16->32 on 6x6 + relu + maxpool2 -> Bw[32*9] ----------
    {
        ull acc[36];
        ull bb = dup2(cw[B2C_OFF + lane]);     // lane = out channel
        #pragma unroll
        for (int p = 0; p < 36; p++) acc[p] = bb;
        const float* w2 = cw + W2_OFF + lane*145;
        for (int ci = 0; ci < 16; ci++) {
            ull wd[9];
            #pragma unroll
            for (int t = 0; t < 9; t++) wd[t] = dup2(w2[ci*9 + t]);
            #pragma unroll
            for (int iy = 0; iy < 6; iy++) {
                ull r[6];
                #pragma unroll
                for (int j = 0; j < 6; j++) r[j] = Aw[ci*36 + iy*6 + j];
                #pragma unroll
                for (int dy = 0; dy < 3; dy++) {
                    int y = iy + 1 - dy;
                    if (y < 0 || y > 5) continue;
                    #pragma unroll
                    for (int dx = 0; dx < 3; dx++) {
                        #pragma unroll
                        for (int x = 0; x < 6; x++) {
                            int xx = x + dx - 1;
                            if (xx < 0 || xx > 5) continue;
                            ffma2(acc[y*6 + x], wd[dy*3 + dx], r[xx]);
                        }
                    }
                }
            }
        }
        #pragma unroll
        for (int py = 0; py < 3; py++)
            #pragma unroll
            for (int px = 0; px < 3; px++) {
                float a0,b0,a1,b1,a2,b2,a3,b3;
                unpk(acc[(2*py)*6   + 2*px  ], a0, b0);
                unpk(acc[(2*py)*6   + 2*px+1], a1, b1);
                unpk(acc[(2*py+1)*6 + 2*px  ], a2, b2);
                unpk(acc[(2*py+1)*6 + 2*px+1], a3, b3);
                float lo = fmaxf(fmaxf(fmaxf(a0,a1), fmaxf(a2,a3)), 0.f);
                float hi = fmaxf(fmaxf(fmaxf(b0,b1), fmaxf(b2,b3)), 0.f);
                Bw[lane*9 + py*3 + px] = pk(lo, hi);
            }
    }
    __syncwarp();

    // ---------- conv3: 32->64 on 3x3, pad1, relu -> feats Aw[0..575] ----------
    {
        ull acc0[9], acc1[9];
        ull b30 = dup2(cw[B3_OFF + lane]);
        ull b31 = dup2(cw[B3_OFF + lane + 32]);
        #pragma unroll
        for (int p = 0; p < 9; p++) { acc0[p] = b30; acc1[p] = b31; }
        const float* w3a = cw + W3_OFF + lane*289;
        const float* w3b = cw + W3_OFF + (lane+32)*289;
        for (int ci = 0; ci < 32; ci++) {
            ull r[9];
            #pragma unroll
            for (int j = 0; j < 9; j++) r[j] = Bw[ci*9 + j];
            #pragma unroll
            for (int t = 0; t < 9; t++) {
                int dy = t/3 - 1, dx = t%3 - 1;
                ull wa = dup2(w3a[ci*9 + t]);
                ull wb = dup2(w3b[ci*9 + t]);
                #pragma unroll
                for (int y = 0; y < 3; y++) {
                    int yy = y + dy; if (yy < 0 || yy > 2) continue;
                    #pragma unroll
                    for (int x = 0; x < 3; x++) {
                        int xx = x + dx; if (xx < 0 || xx > 2) continue;
                        ffma2(acc0[y*3+x], wa, r[yy*3+xx]);
                        ffma2(acc1[y*3+x], wb, r[yy*3+xx]);
                    }
                }
            }
        }
        #pragma unroll
        for (int p = 0; p < 9; p++) {
            Aw[lane*9 + p]      = relu2(acc0[p]);
            Aw[(lane+32)*9 + p] = relu2(acc1[p]);
        }
    }

    // ---------- FC1: pt1 (584->128) + cf1 (584->64), K-tiled via shared ----------
    // thread (og = tid&31, pr = wid): pt outs og*4..og*4+3, cf outs og*2, og*2+1
    const int og = lane;
    const int pr = wid;
    ull aP0=0, aP1=0, aP2=0, aP3=0, aC0=0, aC1=0;
    float* wtile = cw;               // [kt][128]
    float* ctile = cw + KT*128;      // [kt][64]
    for (int k0 = 0; k0 < 584; k0 += KT) {
        int kt = min(KT, 584 - k0);
        __syncthreads();                              // conv done / prev tile done
        for (int i = tid; i < kt*128; i += THREADS) wtile[i] = ptw1[k0*128 + i];
        for (int i = tid; i < kt*64;  i += THREADS) ctile[i] = cfw1[k0*64  + i];
        __syncthreads();
        const ull* fp = A2u + pr*585 + k0;
        #pragma unroll 4
        for (int kk = 0; kk < kt; kk++) {
            ull f = fp[kk];                            // broadcast
            float4 wp = *(const float4*)(wtile + kk*128 + og*4);
            float2 wc = *(const float2*)(ctile + kk*64  + og*2);
            ffma2(aP0, dup2(wp.x), f);
            ffma2(aP1, dup2(wp.y), f);
            ffma2(aP2, dup2(wp.z), f);
            ffma2(aP3, dup2(wp.w), f);
            ffma2(aC0, dup2(wc.x), f);
            ffma2(aC1, dup2(wc.y), f);
        }
    }
    // epilogue: bias + relu -> T1, C1 (in B2u; pair pr owned by this warp)
    {
        float lo, hi, b;
        b = ptb1[og*4+0]; unpk(aP0, lo, hi);
        B2u[T1_BASE + pr*128 + og*4+0] = pk(fmaxf(lo+b,0.f), fmaxf(hi+b,0.f));
        b = ptb1[og*4+1]; unpk(aP1, lo, hi);
        B2u[T1_BASE + pr*128 + og*4+1] = pk(fmaxf(lo+b,0.f), fmaxf(hi+b,0.f));
        b = ptb1[og*4+2]; unpk(aP2, lo, hi);
        B2u[T1_BASE + pr*128 + og*4+2] = pk(fmaxf(lo+b,0.f), fmaxf(hi+b,0.f));
        b = ptb1[og*4+3]; unpk(aP3, lo, hi);
        B2u[T1_BASE + pr*128 + og*4+3] = pk(fmaxf(lo+b,0.f), fmaxf(hi+b,0.f));
        b = cfb1[og*2+0]; unpk(aC0, lo, hi);
        B2u[C1_BASE + pr*65 + og*2+0] = pk(fmaxf(lo+b,0.f), fmaxf(hi+b,0.f));
        b = cfb1[og*2+1]; unpk(aC1, lo, hi);
        B2u[C1_BASE + pr*65 + og*2+1] = pk(fmaxf(lo+b,0.f), fmaxf(hi+b,0.f));
    }

    // ---------- head weights -> shared (cw reusable) ----------
    __syncthreads();
    for (int i = tid; i < 128*64; i += THREADS) cw[W2S + i] = ptw2[i];
    if (tid < 128) cw[W3S + tid] = ptw3[tid];
    else if (tid >= 128 && tid < 192) cw[B2SH + tid - 128] = ptb2[tid - 128];
    else if (tid == 192) { cw[B3SH] = ptb3[0]; cw[B3SH+1] = ptb3[1]; cw[CB2S] = cfb2[0]; }
    else if (tid >= 256 && tid < 320) cw[CW2S + tid - 256] = cfw2[tid - 256];
    __syncthreads();

    // ---------- pt2: 128->64, relu (warp-per-pair) ----------
    {
        ull a0 = 0, a1 = 0;
        #pragma unroll 4
        for (int k = 0; k < 128; k++) {
            ull f = B2u[T1_BASE + pr*128 + k];         // broadcast
            ffma2(a0, dup2(cw[W2S + k*64 + lane]),      f);
            ffma2(a1, dup2(cw[W2S + k*64 + lane + 32]), f);
        }
        float lo, hi, b;
        b = cw[B2SH + lane];      unpk(a0, lo, hi);
        B2u[T2_BASE + pr*65 + lane]      = pk(fmaxf(lo+b,0.f), fmaxf(hi+b,0.f));
        b = cw[B2SH + lane + 32]; unpk(a1, lo, hi);
        B2u[T2_BASE + pr*65 + lane + 32] = pk(fmaxf(lo+b,0.f), fmaxf(hi+b,0.f));
    }
    __syncwarp();

    // ---------- pt3 (64->2) + softmax, cf2 (64->1) + sigmoid ----------
    {
        ull f0 = B2u[T2_BASE + pr*65 + lane];
        ull f1 = B2u[T2_BASE + pr*65 + lane + 32];
        ull g0 = B2u[C1_BASE + pr*65 + lane];
        ull g1 = B2u[C1_BASE + pr*65 + lane + 32];
        ull l0 = 0, l1 = 0, cc = 0;
        ffma2(l0, dup2(cw[W3S + lane*2 + 0]), f0);
        ffma2(l1, dup2(cw[W3S + lane*2 + 1]), f0);
        ffma2(l0, dup2(cw[W3S + (lane+32)*2 + 0]), f1);
        ffma2(l1, dup2(cw[W3S + (lane+32)*2 + 1]), f1);
        ffma2(cc, dup2(cw[CW2S + lane]),      g0);
        ffma2(cc, dup2(cw[CW2S + lane + 32]), g1);
        #pragma unroll
        for (int i = 16; i > 0; i >>= 1) {
            l0 = fadd2(l0, __shfl_xor_sync(0xffffffffu, l0, i));
            l1 = fadd2(l1, __shfl_xor_sync(0xffffffffu, l1, i));
            cc = fadd2(cc, __shfl_xor_sync(0xffffffffu, cc, i));
        }
        if (lane == 0) {
            float l0a,l0b,l1a,l1b,ca,cb;
            unpk(l0, l0a, l0b); unpk(l1, l1a, l1b); unpk(cc, ca, cb);
            float b0 = cw[B3SH], b1 = cw[B3SH+1], bc = cw[CB2S];
            // sample s0
            if (s0 < nsamp) {
                float la = l0a + b0, lb = l1a + b1;
                float m = fmaxf(la, lb);
                float e0 = expf(la - m), e1 = expf(lb - m);
                float inv = 1.f / (e0 + e1);
                gout[(size_t)s0*3 + 0] = e0 * inv;
                gout[(size_t)s0*3 + 1] = e1 * inv;
                gout[(size_t)s0*3 + 2] = 1.f / (1.f + expf(-(ca + bc)));
            }
            // sample s0+1
            if (s0 + 1 < nsamp) {
                float la = l0b + b0, lb = l1b + b1;
                float m = fmaxf(la, lb);
                float e0 = expf(la - m), e1 = expf(lb - m);
                float inv = 1.f / (e0 + e1);
                gout[(size_t)(s0+1)*3 + 0] = e0 * inv;
                gout[(size_t)(s0+1)*3 + 1] = e1 * inv;
                gout[(size_t)(s0+1)*3 + 2] = 1.f / (1.f + expf(-(cb + bc)));
            }
        }
    }
}

extern "C" void kernel_launch(void* const* d_in, const int* in_sizes, int n_in,
                              void* d_out, int out_size) {
    const float* board = (const float*)d_in[0];
    // d_in[1] = target_positions (int64) — mathematically unused
    const float* c1w = (const float*)d_in[2];
    const float* c1b = (const float*)d_in[3];
    const float* c2w = (const float*)d_in[4];
    const float* c2b = (const float*)d_in[5];
    const float* c3w = (const float*)d_in[6];
    const float* c3b = (const float*)d_in[7];
    const float* qp  = (const float*)d_in[8];
    const float* ptw1 = (const float*)d_in[9];
    const float* ptb1 = (const float*)d_in[10];
    const float* ptw2 = (const float*)d_in[11];
    const float* ptb2 = (const float*)d_in[12];
    const float* ptw3 = (const float*)d_in[13];
    const float* ptb3 = (const float*)d_in[14];
    const float* cfw1 = (const float*)d_in[15];
    const float* cfb1 = (const float*)d_in[16];
    const float* cfw2 = (const float*)d_in[17];
    const float* cfb2 = (const float*)d_in[18];
    float* gout = (float*)d_out;

    int nsamp = in_sizes[0] / 108;
    int blocks = (nsamp + SPB - 1) / SPB;

    cudaFuncSetAttribute(cqcnn_kernel,
                         cudaFuncAttributeMaxDynamicSharedMemorySize, SMEM_BYTES);
    cqcnn_kernel<<<blocks, THREADS, SMEM_BYTES>>>(
        board, c1w, c1b, c2w, c2b, c3w, c3b, qp,
        ptw1, ptb1, ptw2, ptb2, ptw3, ptb3,
        cfw1, cfb1, cfw2, cfb2, gout, nsamp);
}

// round 4
// speedup vs baseline: 1.1001x; 1.1001x over previous
#include <cuda_runtime.h>
#include <math.h>

typedef unsigned long long ull;
struct u2v { ull x, y; };

#define THREADS 512
#define SPB 32
#define KT 48

// X region (floats): conv weights, later FC1 scratch (ull), later head weights
#define W1_OFF  0
#define B1_OFF  432
#define W2_OFF  448      // 32*145
#define B2C_OFF 5088
#define W3_OFF  5120     // 64*289
#define B3_OFF  23616
#define X_FLOATS 23680
#define X_BYTES (X_FLOATS * 4)            // 94720

#define A_ULL 10512                        // FT[584][18] ; conv1 acts overlap rows 0..575
#define A_BYTES (A_ULL * 8)                // 84096
#define B_ULL 5120                         // per-pair 320; later FC1 tiles / T1,T2,C1
#define B_BYTES (B_ULL * 8)                // 40960
#define SMEM_BYTES (X_BYTES + A_BYTES + B_BYTES)   // 219776

#define FT_ST 18

// B-region ull offsets after FC1
#define T1O 0        // 16*128
#define T2O 2048     // 16*66
#define C1O 3104     // 16*66

// head weights in X floats
#define W2S  0
#define W3S  8192
#define B2SH 8320
#define B3SH 8384
#define CW2S 8386
#define CB2S 8450

__device__ __forceinline__ ull dup2(float w) {
    ull r; unsigned u = __float_as_uint(w);
    asm("mov.b64 %0, {%1, %1};" : "=l"(r) : "r"(u));
    return r;
}
__device__ __forceinline__ ull pk(float lo, float hi) {
    ull r;
    asm("mov.b64 %0, {%1, %2};" : "=l"(r)
        : "r"(__float_as_uint(lo)), "r"(__float_as_uint(hi)));
    return r;
}
__device__ __forceinline__ void unpk(ull v, float& lo, float& hi) {
    unsigned a, b;
    asm("mov.b64 {%0, %1}, %2;" : "=r"(a), "=r"(b) : "l"(v));
    lo = __uint_as_float(a); hi = __uint_as_float(b);
}
__device__ __forceinline__ void ffma2(ull& d, ull a, ull b) {
    asm("fma.rn.f32x2 %0, %1, %2, %0;" : "+l"(d) : "l"(a), "l"(b));
}
__device__ __forceinline__ ull fadd2(ull a, ull b) {
    ull r;
    asm("add.rn.f32x2 %0, %1, %2;" : "=l"(r) : "l"(a), "l"(b));
    return r;
}
__device__ __forceinline__ ull relu2(ull v) {
    float lo, hi; unpk(v, lo, hi);
    return pk(fmaxf(lo, 0.f), fmaxf(hi, 0.f));
}

__global__ void __launch_bounds__(THREADS, 1)
cqcnn_kernel(const float* __restrict__ gin,
             const float* __restrict__ c1w, const float* __restrict__ c1b,
             const float* __restrict__ c2w, const float* __restrict__ c2b,
             const float* __restrict__ c3w, const float* __restrict__ c3b,
             const float* __restrict__ qp,
             const float* __restrict__ ptw1, const float* __restrict__ ptb1,
             const float* __restrict__ ptw2, const float* __restrict__ ptb2,
             const float* __restrict__ ptw3, const float* __restrict__ ptb3,
             const float* __restrict__ cfw1, const float* __restrict__ cfb1,
             const float* __restrict__ cfw2, const float* __restrict__ cfb2,
             float* __restrict__ gout, int nsamp)
{
    extern __shared__ unsigned char smem[];
    float* cw = (float*)smem;                      // X
    ull*  Au  = (ull*)(smem + X_BYTES);            // A: conv1 acts + FT
    ull*  Bu  = (ull*)(smem + X_BYTES + A_BYTES);  // B
    ull*  Xu  = (ull*)smem;                        // X as ull (scratch)

    const int tid  = threadIdx.x;
    const int wid  = tid >> 5;
    const int lane = tid & 31;

    // ---------- conv weights -> X ----------
    for (int i = tid; i < 16*27;  i += THREADS) cw[W1_OFF + i] = c1w[i];
    for (int i = tid; i < 32*144; i += THREADS)
        cw[W2_OFF + (i/144)*145 + (i%144)] = c2w[i];
    for (int i = tid; i < 64*288; i += THREADS)
        cw[W3_OFF + (i/288)*289 + (i%288)] = c3w[i];
    if (tid < 16) cw[B1_OFF + tid] = c1b[tid];
    else if (tid >= 64  && tid < 96)  cw[B2C_OFF + tid - 64]  = c2b[tid - 64];
    else if (tid >= 128 && tid < 192) cw[B3_OFF  + tid - 128] = c3b[tid - 128];

    // ---------- load sample pair (interleaved f32x2) ----------
    const int s0  = blockIdx.x * SPB + wid * 2;
    const int s0c = min(s0,     nsamp - 1);
    const int s1c = min(s0 + 1, nsamp - 1);
    ull* Bw = Bu + wid * 320;     // input(108), later pooled (32 ch x stride 10)
    ull* Aw = Au + wid * 576;     // conv1 out
    for (int i = lane; i < 108; i += 32)
        Bw[i] = pk(gin[(size_t)s0c * 108 + i], gin[(size_t)s1c * 108 + i]);
    __syncthreads();

    // ---------- quantum feature -> FT rows 576..583 (disjoint from conv1 acts) ----------
    if (lane < 8) {
        float xl, xh, nl, nh;
        unpk(Bw[lane], xl, xh);
        unpk(Bw[(lane + 1) & 7], nl, nh);
        float ql = 0.f, qh = 0.f;
        #pragma unroll
        for (int l = 0; l < 3; l++) {
            float r0 = qp[(l*8 + lane)*3 + 0];
            float r1 = qp[(l*8 + lane)*3 + 1];
            float r2 = qp[(l*8 + lane)*3 + 2];
            ql = sinf(r0*xl) * cosf(r1*nl) + tanhf(r2*ql);
            qh = sinf(r0*xh) * cosf(r1*nh) + tanhf(r2*qh);
        }
        Au[(size_t)(576 + lane) * FT_ST + wid] = pk(ql, qh);
    }

    // ---------- conv1: 3->16, 6x6, pad1, relu -> Aw ----------
    for (int it = 0; it < 18; it++) {
        int item = it*32 + lane;
        int co  = item / 36;
        int pos = item - co*36;
        int y = pos / 6, x = pos - (pos/6)*6;
        ull acc = dup2(cw[B1_OFF + co]);
        const float* wr1 = cw + W1_OFF + co*27;
        #pragma unroll
        for (int dy = 0; dy < 3; dy++) {
            int yy = y + dy - 1;
            bool yok = (yy >= 0) && (yy < 6);
            #pragma unroll
            for (int dx = 0; dx < 3; dx++) {
                int xx = x + dx - 1;
                if (yok && xx >= 0 && xx < 6) {
                    #pragma unroll
                    for (int ci = 0; ci < 3; ci++)
                        ffma2(acc, dup2(wr1[ci*9 + dy*3 + dx]),
                              Bw[ci*36 + yy*6 + xx]);
                }
            }
        }
        Aw[item] = relu2(acc);
    }
    __syncwarp();

    // ---------- conv2: 16->32 + relu + maxpool -> Bw[ch*10 + p] ----------
    {
        ull acc[36];
        ull bb = dup2(cw[B2C_OFF + lane]);
        #pragma unroll
        for (int p = 0; p < 36; p++) acc[p] = bb;
        const float* w2 = cw + W2_OFF + lane*145;
        for (int ci = 0; ci < 16; ci++) {
            ull wd[9];
            #pragma unroll
            for (int t = 0; t < 9; t++) wd[t] = dup2(w2[ci*9 + t]);
            #pragma unroll
            for (int iy = 0; iy < 6; iy++) {
                ull r[6];
                u2v v0 = *(const u2v*)(Aw + ci*36 + iy*6 + 0);
                u2v v1 = *(const u2v*)(Aw + ci*36 + iy*6 + 2);
                u2v v2 = *(const u2v*)(Aw + ci*36 + iy*6 + 4);
                r[0]=v0.x; r[1]=v0.y; r[2]=v1.x; r[3]=v1.y; r[4]=v2.x; r[5]=v2.y;
                #pragma unroll
                for (int dy = 0; dy < 3; dy++) {
                    int y = iy + 1 - dy;
                    if (y < 0 || y > 5) continue;
                    #pragma unroll
                    for (int dx = 0; dx < 3; dx++) {
                        #pragma unroll
                        for (int x = 0; x < 6; x++) {
                            int xx = x + dx - 1;
                            if (xx < 0 || xx > 5) continue;
                            ffma2(acc[y*6 + x], wd[dy*3 + dx], r[xx]);
                        }
                    }
                }
            }
        }
        #pragma unroll
        for (int py = 0; py < 3; py++)
            #pragma unroll
            for (int px = 0; px < 3; px++) {
                float a0,b0,a1,b1,a2,b2,a3,b3;
                unpk(acc[(2*py)*6   + 2*px  ], a0, b0);
                unpk(acc[(2*py)*6   + 2*px+1], a1, b1);
                unpk(acc[(2*py+1)*6 + 2*px  ], a2, b2);
                unpk(acc[(2*py+1)*6 + 2*px+1], a3, b3);
                float lo = fmaxf(fmaxf(fmaxf(a0,a1), fmaxf(a2,a3)), 0.f);
                float hi = fmaxf(fmaxf(fmaxf(b0,b1), fmaxf(b2,b3)), 0.f);
                Bw[lane*10 + py*3 + px] = pk(lo, hi);
            }
    }
    __syncthreads();   // all conv1 acts dead -> FT writes may begin

    // ---------- conv3: 32->64, 3x3, pad1, relu -> FT[k][pair] ----------
    {
        ull acc0[9], acc1[9];
        ull b30 = dup2(cw[B3_OFF + lane]);
        ull b31 = dup2(cw[B3_OFF + lane + 32]);
        #pragma unroll
        for (int p = 0; p < 9; p++) { acc0[p] = b30; acc1[p] = b31; }
        const float* w3a = cw + W3_OFF + lane*289;
        const float* w3b = cw + W3_OFF + (lane+32)*289;
        for (int ci = 0; ci < 32; ci++) {
            ull r[9];
            u2v v0 = *(const u2v*)(Bw + ci*10 + 0);
            u2v v1 = *(const u2v*)(Bw + ci*10 + 2);
            u2v v2 = *(const u2v*)(Bw + ci*10 + 4);
            u2v v3 = *(const u2v*)(Bw + ci*10 + 6);
            r[0]=v0.x; r[1]=v0.y; r[2]=v1.x; r[3]=v1.y;
            r[4]=v2.x; r[5]=v2.y; r[6]=v3.x; r[7]=v3.y;
            r[8]=Bw[ci*10 + 8];
            #pragma unroll
            for (int t = 0; t < 9; t++) {
                int dy = t/3 - 1, dx = t%3 - 1;
                ull wa = dup2(w3a[ci*9 + t]);
                ull wb = dup2(w3b[ci*9 + t]);
                #pragma unroll
                for (int y = 0; y < 3; y++) {
                    int yy = y + dy; if (yy < 0 || yy > 2) continue;
                    #pragma unroll
                    for (int x = 0; x < 3; x++) {
                        int xx = x + dx; if (xx < 0 || xx > 2) continue;
                        ffma2(acc0[y*3+x], wa, r[yy*3+xx]);
                        ffma2(acc1[y*3+x], wb, r[yy*3+xx]);
                    }
                }
            }
        }
        #pragma unroll
        for (int p = 0; p < 9; p++) {
            Au[(size_t)(lane*9 + p)      * FT_ST + wid] = relu2(acc0[p]);
            Au[(size_t)((lane+32)*9 + p) * FT_ST + wid] = relu2(acc1[p]);
        }
    }
    __syncthreads();   // FT complete; B region free

    // ---------- FC1: pt1(584->128)+cf1(584->64), tiled, pair-reuse x4 ----------
    // thread = og(lane: pt outs og*4..+3, cf outs og*2..+1) x sg(4 pairs) x kc(K-split/4)
    const int og = lane;
    const int sg = (tid >> 5) & 3;
    const int kc = tid >> 7;
    float* wt = (float*)Bu;            // [kt][128]
    float* ct = wt + KT*128;           // [kt][64]
    ull acc[24];
    #pragma unroll
    for (int a = 0; a < 24; a++) acc[a] = 0ull;

    for (int k0 = 0; k0 < 584; k0 += KT) {
        int kt = min(KT, 584 - k0);
        __syncthreads();
        for (int i = tid; i < kt*128; i += THREADS) wt[i] = ptw1[k0*128 + i];
        for (int i = tid; i < kt*64;  i += THREADS) ct[i] = cfw1[k0*64  + i];
        __syncthreads();
        int kb = kc * (kt >> 2), ke = kb + (kt >> 2);
        #pragma unroll 2
        for (int kk = kb; kk < ke; kk++) {
            int k = k0 + kk;
            u2v v0 = *(const u2v*)(Au + (size_t)k*FT_ST + sg*4);
            u2v v1 = *(const u2v*)(Au + (size_t)k*FT_ST + sg*4 + 2);
            ull f0 = v0.x, f1 = v0.y, f2 = v1.x, f3 = v1.y;
            float4 wp = *(const float4*)(wt + kk*128 + og*4);
            float2 wc = *(const float2*)(ct + kk*64  + og*2);
            ull w0 = dup2(wp.x), w1 = dup2(wp.y), w2d = dup2(wp.z);
            ull w3d = dup2(wp.w), w4 = dup2(wc.x), w5 = dup2(wc.y);
            ffma2(acc[0],  w0,  f0); ffma2(acc[1],  w1,  f0);
            ffma2(acc[2],  w2d, f0); ffma2(acc[3],  w3d, f0);
            ffma2(acc[4],  w4,  f0); ffma2(acc[5],  w5,  f0);
            ffma2(acc[6],  w0,  f1); ffma2(acc[7],  w1,  f1);
            ffma2(acc[8],  w2d, f1); ffma2(acc[9],  w3d, f1);
            ffma2(acc[10], w4,  f1); ffma2(acc[11], w5,  f1);
            ffma2(acc[12], w0,  f2); ffma2(acc[13], w1,  f2);
            ffma2(acc[14], w2d, f2); ffma2(acc[15], w3d, f2);
            ffma2(acc[16], w4,  f2); ffma2(acc[17], w5,  f2);
            ffma2(acc[18], w0,  f3); ffma2(acc[19], w1,  f3);
            ffma2(acc[20], w2d, f3); ffma2(acc[21], w3d, f3);
            ffma2(acc[22], w4,  f3); ffma2(acc[23], w5,  f3);
        }
    }
    __syncthreads();   // all compute done; wt dead, X conv weights dead
    if (kc > 0) {
        ull* sp = Xu + (size_t)((kc-1)*128 + sg*32 + og) * 25;
        #pragma unroll
        for (int a = 0; a < 24; a++) sp[a] = acc[a];
    }
    __syncthreads();
    if (kc == 0) {
        #pragma unroll
        for (int c = 0; c < 3; c++) {
            const ull* sp = Xu + (size_t)(c*128 + sg*32 + og) * 25;
            #pragma unroll
            for (int a = 0; a < 24; a++) acc[a] = fadd2(acc[a], sp[a]);
        }
        #pragma unroll
        for (int i = 0; i < 4; i++) {
            int pr2 = sg*4 + i;
            #pragma unroll
            for (int j = 0; j < 4; j++) {
                float b = ptb1[og*4 + j];
                float lo, hi; unpk(acc[i*6 + j], lo, hi);
                Bu[T1O + pr2*128 + og*4 + j] = pk(fmaxf(lo+b,0.f), fmaxf(hi+b,0.f));
            }
            #pragma unroll
            for (int j = 0; j < 2; j++) {
                float b = cfb1[og*2 + j];
                float lo, hi; unpk(acc[i*6 + 4 + j], lo, hi);
                Bu[C1O + pr2*66 + og*2 + j] = pk(fmaxf(lo+b,0.f), fmaxf(hi+b,0.f));
            }
        }
    }
    __syncthreads();   // T1/C1 ready; X scratch dead

    // ---------- head weights -> X ----------
    for (int i = tid; i < 128*64; i += THREADS) cw[W2S + i] = ptw2[i];
    if (tid < 128) cw[W3S + tid] = ptw3[tid];
    else if (tid >= 128 && tid < 192) cw[B2SH + tid - 128] = ptb2[tid - 128];
    else if (tid == 192) { cw[B3SH] = ptb3[0]; cw[B3SH+1] = ptb3[1]; cw[CB2S] = cfb2[0]; }
    else if (tid >= 256 && tid < 320) cw[CW2S + tid - 256] = cfw2[tid - 256];
    __syncthreads();

    // ---------- pt2: 128->64, relu (warp-per-pair) ----------
    const int pr = wid;
    {
        ull a0 = 0, a1 = 0;
        #pragma unroll 4
        for (int k = 0; k < 128; k++) {
            ull f = Bu[T1O + pr*128 + k];
            ffma2(a0, dup2(cw[W2S + k*64 + lane]),      f);
            ffma2(a1, dup2(cw[W2S + k*64 + lane + 32]), f);
        }
        float lo, hi, b;
        b = cw[B2SH + lane];      unpk(a0, lo, hi);
        Bu[T2O + pr*66 + lane]      = pk(fmaxf(lo+b,0.f), fmaxf(hi+b,0.f));
        b = cw[B2SH + lane + 32]; unpk(a1, lo, hi);
        Bu[T2O + pr*66 + lane + 32] = pk(fmaxf(lo+b,0.f), fmaxf(hi+b,0.f));
    }
    __syncwarp();

    // ---------- pt3 + softmax, cf2 + sigmoid ----------
    {
        ull f0 = Bu[T2O + pr*66 + lane];
        ull f1 = Bu[T2O + pr*66 + lane + 32];
        ull g0 = Bu[C1O + pr*66 + lane];
        ull g1 = Bu[C1O + pr*66 + lane + 32];
        ull l0 = 0, l1 = 0, cc = 0;
        ffma2(l0, dup2(cw[W3S + lane*2 + 0]), f0);
        ffma2(l1, dup2(cw[W3S + lane*2 + 1]), f0);
        ffma2(l0, dup2(cw[W3S + (lane+32)*2 + 0]), f1);
        ffma2(l1, dup2(cw[W3S + (lane+32)*2 + 1]), f1);
        ffma2(cc, dup2(cw[CW2S + lane]),      g0);
        ffma2(cc, dup2(cw[CW2S + lane + 32]), g1);
        #pragma unroll
        for (int i = 16; i > 0; i >>= 1) {
            l0 = fadd2(l0, __shfl_xor_sync(0xffffffffu, l0, i));
            l1 = fadd2(l1, __shfl_xor_sync(0xffffffffu, l1, i));
            cc = fadd2(cc, __shfl_xor_sync(0xffffffffu, cc, i));
        }
        if (lane == 0) {
            float l0a,l0b,l1a,l1b,ca,cb;
            unpk(l0, l0a, l0b); unpk(l1, l1a, l1b); unpk(cc, ca, cb);
            float b0 = cw[B3SH], b1 = cw[B3SH+1], bc = cw[CB2S];
            if (s0 < nsamp) {
                float la = l0a + b0, lb = l1a + b1;
                float m = fmaxf(la, lb);
                float e0 = expf(la - m), e1 = expf(lb - m);
                float inv = 1.f / (e0 + e1);
                gout[(size_t)s0*3 + 0] = e0 * inv;
                gout[(size_t)s0*3 + 1] = e1 * inv;
                gout[(size_t)s0*3 + 2] = 1.f / (1.f + expf(-(ca + bc)));
            }
            if (s0 + 1 < nsamp) {
                float la = l0b + b0, lb = l1b + b1;
                float m = fmaxf(la, lb);
                float e0 = expf(la - m), e1 = expf(lb - m);
                float inv = 1.f / (e0 + e1);
                gout[(size_t)(s0+1)*3 + 0] = e0 * inv;
                gout[(size_t)(s0+1)*3 + 1] = e1 * inv;
                gout[(size_t)(s0+1)*3 + 2] = 1.f / (1.f + expf(-(cb + bc)));
            }
        }
    }
}

extern "C" void kernel_launch(void* const* d_in, const int* in_sizes, int n_in,
                              void* d_out, int out_size) {
    const float* board = (const float*)d_in[0];
    const float* c1w = (const float*)d_in[2];
    const float* c1b = (const float*)d_in[3];
    const float* c2w = (const float*)d_in[4];
    const float* c2b = (const float*)d_in[5];
    const float* c3w = (const float*)d_in[6];
    const float* c3b = (const float*)d_in[7];
    const float* qp  = (const float*)d_in[8];
    const float* ptw1 = (const float*)d_in[9];
    const float* ptb1 = (const float*)d_in[10];
    const float* ptw2 = (const float*)d_in[11];
    const float* ptb2 = (const float*)d_in[12];
    const float* ptw3 = (const float*)d_in[13];
    const float* ptb3 = (const float*)d_in[14];
    const float* cfw1 = (const float*)d_in[15];
    const float* cfb1 = (const float*)d_in[16];
    const float* cfw2 = (const float*)d_in[17];
    const float* cfb2 = (const float*)d_in[18];
    float* gout = (float*)d_out;

    int nsamp = in_sizes[0] / 108;
    int blocks = (nsamp + SPB - 1) / SPB;

    cudaFuncSetAttribute(cqcnn_kernel,
                         cudaFuncAttributeMaxDynamicSharedMemorySize, SMEM_BYTES);
    cqcnn_kernel<<<blocks, THREADS, SMEM_BYTES>>>(
        board, c1w, c1b, c2w, c2b, c3w, c3b, qp,
        ptw1, ptb1, ptw2, ptb2, ptw3, ptb3,
        cfw1, cfb1, cfw2, cfb2, gout, nsamp);
}

// round 5
// speedup vs baseline: 1.2464x; 1.1330x over previous
#include <cuda_runtime.h>
#include <math.h>

typedef unsigned long long ull;
struct u2v { ull x, y; };

#define THREADS 512
#define SPB 32
#define KT 120

// X region (floats 23680): conv wts -> FC1 tiles -> reduction scratch(ull) -> head wts
#define W1_OFF  0
#define B1_OFF  432
#define W2_OFF  448      // 32*145
#define B2C_OFF 5088
#define W3_OFF  5120     // 64*289
#define B3_OFF  23616
#define X_FLOATS 23680
#define X_BYTES (X_FLOATS * 4)             // 94720

#define PAIR_ST 592
#define A_ULL (16 * PAIR_ST)               // per-pair feats/conv1 acts
#define A_BYTES (A_ULL * 8)                // 75776
#define B_ULL 5120                         // per-pair input/pooled; later T1,T2,C1
#define B_BYTES (B_ULL * 8)                // 40960
#define SMEM_BYTES (X_BYTES + A_BYTES + B_BYTES)   // 211456

// B-region ull offsets after convs
#define T1O 0        // 16*128
#define T2O 2048     // 16*66
#define C1O 3104     // 16*66

// head weights in X floats
#define W2S  0
#define W3S  8192
#define B2SH 8320
#define B3SH 8384
#define CW2S 8386
#define CB2S 8450

__device__ __forceinline__ ull dup2(float w) {
    ull r; unsigned u = __float_as_uint(w);
    asm("mov.b64 %0, {%1, %1};" : "=l"(r) : "r"(u));
    return r;
}
__device__ __forceinline__ ull pk(float lo, float hi) {
    ull r;
    asm("mov.b64 %0, {%1, %2};" : "=l"(r)
        : "r"(__float_as_uint(lo)), "r"(__float_as_uint(hi)));
    return r;
}
__device__ __forceinline__ void unpk(ull v, float& lo, float& hi) {
    unsigned a, b;
    asm("mov.b64 {%0, %1}, %2;" : "=r"(a), "=r"(b) : "l"(v));
    lo = __uint_as_float(a); hi = __uint_as_float(b);
}
__device__ __forceinline__ void ffma2(ull& d, ull a, ull b) {
    asm("fma.rn.f32x2 %0, %1, %2, %0;" : "+l"(d) : "l"(a), "l"(b));
}
__device__ __forceinline__ ull fadd2(ull a, ull b) {
    ull r;
    asm("add.rn.f32x2 %0, %1, %2;" : "=l"(r) : "l"(a), "l"(b));
    return r;
}
__device__ __forceinline__ ull relu2(ull v) {
    float lo, hi; unpk(v, lo, hi);
    return pk(fmaxf(lo, 0.f), fmaxf(hi, 0.f));
}

// conv1 half: out rows YB..YB+2 for channel co; reads input Bw, writes Aw.
template<int YB>
__device__ __forceinline__ void conv1_half(const float* cw, const ull* Bw,
                                           ull* Aw, int co) {
    ull acc[18];
    ull bb = dup2(cw[B1_OFF + co]);
    #pragma unroll
    for (int p = 0; p < 18; p++) acc[p] = bb;
    const float* wr = cw + W1_OFF + co*27;
    #pragma unroll
    for (int ci = 0; ci < 3; ci++) {
        ull wd[9];
        #pragma unroll
        for (int t = 0; t < 9; t++) wd[t] = dup2(wr[ci*9 + t]);
        #pragma unroll
        for (int iy = YB - 1; iy <= YB + 3; iy++) {
            if (iy < 0 || iy > 5) continue;
            ull r[6];
            u2v v0 = *(const u2v*)(Bw + ci*36 + iy*6 + 0);
            u2v v1 = *(const u2v*)(Bw + ci*36 + iy*6 + 2);
            u2v v2 = *(const u2v*)(Bw + ci*36 + iy*6 + 4);
            r[0]=v0.x; r[1]=v0.y; r[2]=v1.x; r[3]=v1.y; r[4]=v2.x; r[5]=v2.y;
            #pragma unroll
            for (int dy = 0; dy < 3; dy++) {
                int y = iy + 1 - dy;
                if (y < YB || y > YB + 2) continue;
                #pragma unroll
                for (int dx = 0; dx < 3; dx++)
                    #pragma unroll
                    for (int x = 0; x < 6; x++) {
                        int xx = x + dx - 1;
                        if (xx < 0 || xx > 5) continue;
                        ffma2(acc[(y - YB)*6 + x], wd[dy*3 + dx], r[xx]);
                    }
            }
        }
    }
    #pragma unroll
    for (int ly = 0; ly < 3; ly++)
        #pragma unroll
        for (int x = 0; x < 6; x++)
            Aw[co*36 + (YB + ly)*6 + x] = relu2(acc[ly*6 + x]);
}

__global__ void __launch_bounds__(THREADS, 1)
cqcnn_kernel(const float* __restrict__ gin,
             const float* __restrict__ c1w, const float* __restrict__ c1b,
             const float* __restrict__ c2w, const float* __restrict__ c2b,
             const float* __restrict__ c3w, const float* __restrict__ c3b,
             const float* __restrict__ qp,
             const float* __restrict__ ptw1, const float* __restrict__ ptb1,
             const float* __restrict__ ptw2, const float* __restrict__ ptb2,
             const float* __restrict__ ptw3, const float* __restrict__ ptb3,
             const float* __restrict__ cfw1, const float* __restrict__ cfb1,
             const float* __restrict__ cfw2, const float* __restrict__ cfb2,
             float* __restrict__ gout, int nsamp)
{
    extern __shared__ unsigned char smem[];
    float* cw = (float*)smem;                      // X
    ull*  Au  = (ull*)(smem + X_BYTES);            // A: per-pair feats
    ull*  Bu  = (ull*)(smem + X_BYTES + A_BYTES);  // B
    ull*  Xu  = (ull*)smem;                        // X as ull (scratch)

    const int tid  = threadIdx.x;
    const int wid  = tid >> 5;
    const int lane = tid & 31;

    // ---------- conv weights -> X (cooperative) ----------
    for (int i = tid; i < 16*27;  i += THREADS) cw[W1_OFF + i] = c1w[i];
    for (int i = tid; i < 32*144; i += THREADS)
        cw[W2_OFF + (i/144)*145 + (i%144)] = c2w[i];
    for (int i = tid; i < 64*288; i += THREADS)
        cw[W3_OFF + (i/288)*289 + (i%288)] = c3w[i];
    if (tid < 16) cw[B1_OFF + tid] = c1b[tid];
    else if (tid >= 64  && tid < 96)  cw[B2C_OFF + tid - 64]  = c2b[tid - 64];
    else if (tid >= 128 && tid < 192) cw[B3_OFF  + tid - 128] = c3b[tid - 128];

    // ---------- per-warp sample pair load ----------
    const int s0  = blockIdx.x * SPB + wid * 2;
    const int s0c = min(s0,     nsamp - 1);
    const int s1c = min(s0 + 1, nsamp - 1);
    ull* Bw = Bu + wid * 320;     // input(108), later pooled (32 ch x stride 10)
    ull* Aw = Au + wid * PAIR_ST; // conv1 acts / feats (per-pair)
    for (int i = lane; i < 108; i += 32)
        Bw[i] = pk(gin[(size_t)s0c * 108 + i], gin[(size_t)s1c * 108 + i]);
    __syncthreads();   // weights visible; input visible (own warp anyway)

    // ================= barrier-free warp-private section =================

    // ---------- quantum feature -> feats[576..583] ----------
    if (lane < 8) {
        float xl, xh, nl, nh;
        unpk(Bw[lane], xl, xh);
        unpk(Bw[(lane + 1) & 7], nl, nh);
        float ql = 0.f, qh = 0.f;
        #pragma unroll
        for (int l = 0; l < 3; l++) {
            float r0 = qp[(l*8 + lane)*3 + 0];
            float r1 = qp[(l*8 + lane)*3 + 1];
            float r2 = qp[(l*8 + lane)*3 + 2];
            ql = sinf(r0*xl) * cosf(r1*nl) + tanhf(r2*ql);
            qh = sinf(r0*xh) * cosf(r1*nh) + tanhf(r2*qh);
        }
        Aw[576 + lane] = pk(ql, qh);
    }

    // ---------- conv1: lane = (co, row-half) ----------
    {
        int co = lane >> 1;
        if (lane & 1) conv1_half<3>(cw, Bw, Aw, co);
        else          conv1_half<0>(cw, Bw, Aw, co);
    }
    __syncwarp();

    // ---------- conv2: 16->32 + relu + maxpool -> Bw[ch*10 + p] ----------
    {
        ull acc[36];
        ull bb = dup2(cw[B2C_OFF + lane]);
        #pragma unroll
        for (int p = 0; p < 36; p++) acc[p] = bb;
        const float* w2 = cw + W2_OFF + lane*145;
        for (int ci = 0; ci < 16; ci++) {
            ull wd[9];
            #pragma unroll
            for (int t = 0; t < 9; t++) wd[t] = dup2(w2[ci*9 + t]);
            #pragma unroll
            for (int iy = 0; iy < 6; iy++) {
                ull r[6];
                u2v v0 = *(const u2v*)(Aw + ci*36 + iy*6 + 0);
                u2v v1 = *(const u2v*)(Aw + ci*36 + iy*6 + 2);
                u2v v2 = *(const u2v*)(Aw + ci*36 + iy*6 + 4);
                r[0]=v0.x; r[1]=v0.y; r[2]=v1.x; r[3]=v1.y; r[4]=v2.x; r[5]=v2.y;
                #pragma unroll
                for (int dy = 0; dy < 3; dy++) {
                    int y = iy + 1 - dy;
                    if (y < 0 || y > 5) continue;
                    #pragma unroll
                    for (int dx = 0; dx < 3; dx++) {
                        #pragma unroll
                        for (int x = 0; x < 6; x++) {
                            int xx = x + dx - 1;
                            if (xx < 0 || xx > 5) continue;
                            ffma2(acc[y*6 + x], wd[dy*3 + dx], r[xx]);
                        }
                    }
                }
            }
        }
        #pragma unroll
        for (int py = 0; py < 3; py++)
            #pragma unroll
            for (int px = 0; px < 3; px++) {
                float a0,b0,a1,b1,a2,b2,a3,b3;
                unpk(acc[(2*py)*6   + 2*px  ], a0, b0);
                unpk(acc[(2*py)*6   + 2*px+1], a1, b1);
                unpk(acc[(2*py+1)*6 + 2*px  ], a2, b2);
                unpk(acc[(2*py+1)*6 + 2*px+1], a3, b3);
                float lo = fmaxf(fmaxf(fmaxf(a0,a1), fmaxf(a2,a3)), 0.f);
                float hi = fmaxf(fmaxf(fmaxf(b0,b1), fmaxf(b2,b3)), 0.f);
                Bw[lane*10 + py*3 + px] = pk(lo, hi);
            }
    }
    __syncwarp();

    // ---------- conv3: 32->64, 3x3, pad1, relu -> feats[0..575] (own pair) ----------
    {
        ull acc0[9], acc1[9];
        ull b30 = dup2(cw[B3_OFF + lane]);
        ull b31 = dup2(cw[B3_OFF + lane + 32]);
        #pragma unroll
        for (int p = 0; p < 9; p++) { acc0[p] = b30; acc1[p] = b31; }
        const float* w3a = cw + W3_OFF + lane*289;
        const float* w3b = cw + W3_OFF + (lane+32)*289;
        for (int ci = 0; ci < 32; ci++) {
            ull r[9];
            u2v v0 = *(const u2v*)(Bw + ci*10 + 0);
            u2v v1 = *(const u2v*)(Bw + ci*10 + 2);
            u2v v2 = *(const u2v*)(Bw + ci*10 + 4);
            u2v v3 = *(const u2v*)(Bw + ci*10 + 6);
            r[0]=v0.x; r[1]=v0.y; r[2]=v1.x; r[3]=v1.y;
            r[4]=v2.x; r[5]=v2.y; r[6]=v3.x; r[7]=v3.y;
            r[8]=Bw[ci*10 + 8];
            #pragma unroll
            for (int t = 0; t < 9; t++) {
                int dy = t/3 - 1, dx = t%3 - 1;
                ull wa = dup2(w3a[ci*9 + t]);
                ull wb = dup2(w3b[ci*9 + t]);
                #pragma unroll
                for (int y = 0; y < 3; y++) {
                    int yy = y + dy; if (yy < 0 || yy > 2) continue;
                    #pragma unroll
                    for (int x = 0; x < 3; x++) {
                        int xx = x + dx; if (xx < 0 || xx > 2) continue;
                        ffma2(acc0[y*3+x], wa, r[yy*3+xx]);
                        ffma2(acc1[y*3+x], wb, r[yy*3+xx]);
                    }
                }
            }
        }
        #pragma unroll
        for (int p = 0; p < 9; p++) {
            Aw[lane*9 + p]        = relu2(acc0[p]);
            Aw[(lane+32)*9 + p]   = relu2(acc1[p]);
        }
    }

    // ================= end warp-private section =================

    // ---------- FC1: pt1(584->128)+cf1(584->64), X-staged tiles, pair-reuse x4 ----------
    const int og = lane;
    const int sg = (tid >> 5) & 3;
    const int kc = tid >> 7;
    float* wt = cw;                    // [kt][128]
    float* ct = cw + KT*128;           // [kt][64]
    ull acc[24];
    #pragma unroll
    for (int a = 0; a < 24; a++) acc[a] = 0ull;

    for (int k0 = 0; k0 < 584; k0 += KT) {
        int kt = min(KT, 584 - k0);
        __syncthreads();   // convs done (first iter) / prev tile consumed
        for (int i = tid; i < kt*128; i += THREADS) wt[i] = ptw1[k0*128 + i];
        for (int i = tid; i < kt*64;  i += THREADS) ct[i] = cfw1[k0*64  + i];
        __syncthreads();
        int kb = kc * (kt >> 2), ke = kb + (kt >> 2);
        #pragma unroll 2
        for (int kk = kb; kk < ke; kk++) {
            int k = k0 + kk;
            ull f0 = Au[(sg*4 + 0)*PAIR_ST + k];
            ull f1 = Au[(sg*4 + 1)*PAIR_ST + k];
            ull f2 = Au[(sg*4 + 2)*PAIR_ST + k];
            ull f3 = Au[(sg*4 + 3)*PAIR_ST + k];
            float4 wp = *(const float4*)(wt + kk*128 + og*4);
            float2 wc = *(const float2*)(ct + kk*64  + og*2);
            ull w0 = dup2(wp.x), w1 = dup2(wp.y), w2d = dup2(wp.z);
            ull w3d = dup2(wp.w), w4 = dup2(wc.x), w5 = dup2(wc.y);
            ffma2(acc[0],  w0,  f0); ffma2(acc[1],  w1,  f0);
            ffma2(acc[2],  w2d, f0); ffma2(acc[3],  w3d, f0);
            ffma2(acc[4],  w4,  f0); ffma2(acc[5],  w5,  f0);
            ffma2(acc[6],  w0,  f1); ffma2(acc[7],  w1,  f1);
            ffma2(acc[8],  w2d, f1); ffma2(acc[9],  w3d, f1);
            ffma2(acc[10], w4,  f1); ffma2(acc[11], w5,  f1);
            ffma2(acc[12], w0,  f2); ffma2(acc[13], w1,  f2);
            ffma2(acc[14], w2d, f2); ffma2(acc[15], w3d, f2);
            ffma2(acc[16], w4,  f2); ffma2(acc[17], w5,  f2);
            ffma2(acc[18], w0,  f3); ffma2(acc[19], w1,  f3);
            ffma2(acc[20], w2d, f3); ffma2(acc[21], w3d, f3);
            ffma2(acc[22], w4,  f3); ffma2(acc[23], w5,  f3);
        }
    }
    __syncthreads();   // tiles dead -> X reusable as reduction scratch
    if (kc > 0) {
        ull* sp = Xu + (size_t)((kc-1)*128 + sg*32 + og) * 25;
        #pragma unroll
        for (int a = 0; a < 24; a++) sp[a] = acc[a];
    }
    __syncthreads();
    if (kc == 0) {
        #pragma unroll
        for (int c = 0; c < 3; c++) {
            const ull* sp = Xu + (size_t)(c*128 + sg*32 + og) * 25;
            #pragma unroll
            for (int a = 0; a < 24; a++) acc[a] = fadd2(acc[a], sp[a]);
        }
        #pragma unroll
        for (int i = 0; i < 4; i++) {
            int pr2 = sg*4 + i;
            #pragma unroll
            for (int j = 0; j < 4; j++) {
                float b = ptb1[og*4 + j];
                float lo, hi; unpk(acc[i*6 + j], lo, hi);
                Bu[T1O + pr2*128 + og*4 + j] = pk(fmaxf(lo+b,0.f), fmaxf(hi+b,0.f));
            }
            #pragma unroll
            for (int j = 0; j < 2; j++) {
                float b = cfb1[og*2 + j];
                float lo, hi; unpk(acc[i*6 + 4 + j], lo, hi);
                Bu[C1O + pr2*66 + og*2 + j] = pk(fmaxf(lo+b,0.f), fmaxf(hi+b,0.f));
            }
        }
    }
    __syncthreads();   // T1/C1 ready; X scratch dead

    // ---------- head weights -> X ----------
    for (int i = tid; i < 128*64; i += THREADS) cw[W2S + i] = ptw2[i];
    if (tid < 128) cw[W3S + tid] = ptw3[tid];
    else if (tid >= 128 && tid < 192) cw[B2SH + tid - 128] = ptb2[tid - 128];
    else if (tid == 192) { cw[B3SH] = ptb3[0]; cw[B3SH+1] = ptb3[1]; cw[CB2S] = cfb2[0]; }
    else if (tid >= 256 && tid < 320) cw[CW2S + tid - 256] = cfw2[tid - 256];
    __syncthreads();

    // ---------- pt2: 128->64, relu (warp-per-pair) ----------
    const int pr = wid;
    {
        ull a0 = 0, a1 = 0;
        #pragma unroll 4
        for (int k = 0; k < 128; k++) {
            ull f = Bu[T1O + pr*128 + k];
            ffma2(a0, dup2(cw[W2S + k*64 + lane]),      f);
            ffma2(a1, dup2(cw[W2S + k*64 + lane + 32]), f);
        }
        float lo, hi, b;
        b = cw[B2SH + lane];      unpk(a0, lo, hi);
        Bu[T2O + pr*66 + lane]      = pk(fmaxf(lo+b,0.f), fmaxf(hi+b,0.f));
        b = cw[B2SH + lane + 32]; unpk(a1, lo, hi);
        Bu[T2O + pr*66 + lane + 32] = pk(fmaxf(lo+b,0.f), fmaxf(hi+b,0.f));
    }
    __syncwarp();

    // ---------- pt3 + softmax, cf2 + sigmoid ----------
    {
        ull f0 = Bu[T2O + pr*66 + lane];
        ull f1 = Bu[T2O + pr*66 + lane + 32];
        ull g0 = Bu[C1O + pr*66 + lane];
        ull g1 = Bu[C1O + pr*66 + lane + 32];
        ull l0 = 0, l1 = 0, cc = 0;
        ffma2(l0, dup2(cw[W3S + lane*2 + 0]), f0);
        ffma2(l1, dup2(cw[W3S + lane*2 + 1]), f0);
        ffma2(l0, dup2(cw[W3S + (lane+32)*2 + 0]), f1);
        ffma2(l1, dup2(cw[W3S + (lane+32)*2 + 1]), f1);
        ffma2(cc, dup2(cw[CW2S + lane]),      g0);
        ffma2(cc, dup2(cw[CW2S + lane + 32]), g1);
        #pragma unroll
        for (int i = 16; i > 0; i >>= 1) {
            l0 = fadd2(l0, __shfl_xor_sync(0xffffffffu, l0, i));
            l1 = fadd2(l1, __shfl_xor_sync(0xffffffffu, l1, i));
            cc = fadd2(cc, __shfl_xor_sync(0xffffffffu, cc, i));
        }
        if (lane == 0) {
            float l0a,l0b,l1a,l1b,ca,cb;
            unpk(l0, l0a, l0b); unpk(l1, l1a, l1b); unpk(cc, ca, cb);
            float b0 = cw[B3SH], b1 = cw[B3SH+1], bc = cw[CB2S];
            if (s0 < nsamp) {
                float la = l0a + b0, lb = l1a + b1;
                float m = fmaxf(la, lb);
                float e0 = expf(la - m), e1 = expf(lb - m);
                float inv = 1.f / (e0 + e1);
                gout[(size_t)s0*3 + 0] = e0 * inv;
                gout[(size_t)s0*3 + 1] = e1 * inv;
                gout[(size_t)s0*3 + 2] = 1.f / (1.f + expf(-(ca + bc)));
            }
            if (s0 + 1 < nsamp) {
                float la = l0b + b0, lb = l1b + b1;
                float m = fmaxf(la, lb);
                float e0 = expf(la - m), e1 = expf(lb - m);
                float inv = 1.f / (e0 + e1);
                gout[(size_t)(s0+1)*3 + 0] = e0 * inv;
                gout[(size_t)(s0+1)*3 + 1] = e1 * inv;
                gout[(size_t)(s0+1)*3 + 2] = 1.f / (1.f + expf(-(cb + bc)));
            }
        }
    }
}

extern "C" void kernel_launch(void* const* d_in, const int* in_sizes, int n_in,
                              void* d_out, int out_size) {
    const float* board = (const float*)d_in[0];
    const float* c1w = (const float*)d_in[2];
    const float* c1b = (const float*)d_in[3];
    const float* c2w = (const float*)d_in[4];
    const float* c2b = (const float*)d_in[5];
    const float* c3w = (const float*)d_in[6];
    const float* c3b = (const float*)d_in[7];
    const float* qp  = (const float*)d_in[8];
    const float* ptw1 = (const float*)d_in[9];
    const float* ptb1 = (const float*)d_in[10];
    const float* ptw2 = (const float*)d_in[11];
    const float* ptb2 = (const float*)d_in[12];
    const float* ptw3 = (const float*)d_in[13];
    const float* ptb3 = (const float*)d_in[14];
    const float* cfw1 = (const float*)d_in[15];
    const float* cfb1 = (const float*)d_in[16];
    const float* cfw2 = (const float*)d_in[17];
    const float* cfb2 = (const float*)d_in[18];
    float* gout = (float*)d_out;

    int nsamp = in_sizes[0] / 108;
    int blocks = (nsamp + SPB - 1) / SPB;

    cudaFuncSetAttribute(cqcnn_kernel,
                         cudaFuncAttributeMaxDynamicSharedMemorySize, SMEM_BYTES);
    cqcnn_kernel<<<blocks, THREADS, SMEM_BYTES>>>(
        board, c1w, c1b, c2w, c2b, c3w, c3b, qp,
        ptw1, ptb1, ptw2, ptb2, ptw3, ptb3,
        cfw1, cfb1, cfw2, cfb2, gout, nsamp);
}